// round 3
// baseline (speedup 1.0000x reference)
#include <cuda_runtime.h>

// LMNN loss on GB300 — MLP-boosted version.
// outputs: [2048, 512, 128] f32, label_inds: [2048, 511] i32, out: scalar f32.
//
// Diagnosis R1/R2: regs capped at 32 -> only ~2 LDG.128 in flight per warp
// -> latency-limited at ~78% DRAM. Fix: manual 8-deep register batch of
// point rows per warp (MLP_eff ~8), contiguous 64-point chunk per warp for
// DRAM locality. launch_bounds(256,5) gives ptxas ~51 regs so the batch
// stays register-resident.

#define NSEG 2048
#define PPS  512
#define DDIM 128
#define NPTS 511   // PPS - 1
#define NTHR 256
#define NWRP 8
#define CHUNK 64   // ceil(511/8)
#define BATCH 8

__global__ void lmnn_init_out(float* out) { *out = 0.0f; }

__device__ __forceinline__ float warp_sum_sq(float4 p, float4 c) {
    const float dx = p.x - c.x;
    const float dy = p.y - c.y;
    const float dz = p.z - c.z;
    const float dw = p.w - c.w;
    float s = dx * dx + dy * dy + dz * dz + dw * dw;
    #pragma unroll
    for (int o = 16; o > 0; o >>= 1)
        s += __shfl_xor_sync(0xffffffffu, s, o);
    return s;
}

__global__ __launch_bounds__(NTHR, 5)
void lmnn_kernel(const float* __restrict__ outputs,
                 const int*   __restrict__ labels,
                 float*       __restrict__ out)
{
    __shared__ float sh_d2[NPTS];
    __shared__ int   sh_same[NPTS];
    __shared__ float sh_red[NWRP];

    const int seg  = blockIdx.x;
    const int tid  = threadIdx.x;
    const int warp = tid >> 5;
    const int lane = tid & 31;

    const float4* base = reinterpret_cast<const float4*>(
        outputs + (size_t)seg * PPS * DDIM);

    // Center row: lane l owns dims [4l, 4l+4). Redundant per warp; L1 hit.
    const float4 c = base[lane];

    // Same-label flags vs label of first point.
    const int* lab = labels + (size_t)seg * NPTS;
    const int lab0 = lab[0];
    for (int j = tid; j < NPTS; j += NTHR)
        sh_same[j] = (lab[j] == lab0);

    // Warp w owns contiguous points [w*64, min(w*64+64, 511)).
    const int jbeg = warp * CHUNK;
    const int jend = min(jbeg + CHUNK, NPTS);

    // Full batches of 8: load all 8 rows first (8 independent LDG.128 in
    // flight per warp), then run the 8 shuffle-reduce chains.
    int j = jbeg;
    for (; j + BATCH <= jend; j += BATCH) {
        float4 p[BATCH];
        #pragma unroll
        for (int k = 0; k < BATCH; k++)
            p[k] = base[(j + k + 1) * (DDIM / 4) + lane];
        #pragma unroll
        for (int k = 0; k < BATCH; k++) {
            const float s = warp_sum_sq(p[k], c);
            if (lane == 0) sh_d2[j + k] = s;
        }
    }
    // Remainder (only warp 7: 63 = 7*8 + 7).
    for (; j < jend; j++) {
        const float4 p = base[(j + 1) * (DDIM / 4) + lane];
        const float s = warp_sum_sq(p, c);
        if (lane == 0) sh_d2[j] = s;
    }
    __syncthreads();

    // pull_d = min d2 over same-label points (j=0 is always same-label).
    float lmin = __int_as_float(0x7f800000);  // +inf
    for (int jj = tid; jj < NPTS; jj += NTHR)
        if (sh_same[jj]) lmin = fminf(lmin, sh_d2[jj]);
    #pragma unroll
    for (int o = 16; o > 0; o >>= 1)
        lmin = fminf(lmin, __shfl_xor_sync(0xffffffffu, lmin, o));
    if (lane == 0) sh_red[warp] = lmin;
    __syncthreads();

    float pull = sh_red[0];
    #pragma unroll
    for (int w = 1; w < NWRP; w++) pull = fminf(pull, sh_red[w]);
    const float margin = 1.0f + pull;

    // push = sum over diff-label points of max(margin - d2, 0).
    float lsum = 0.0f;
    for (int jj = tid; jj < NPTS; jj += NTHR)
        if (!sh_same[jj]) lsum += fmaxf(margin - sh_d2[jj], 0.0f);
    #pragma unroll
    for (int o = 16; o > 0; o >>= 1)
        lsum += __shfl_xor_sync(0xffffffffu, lsum, o);
    __syncthreads();          // all reads of sh_red (pull) done before reuse
    if (lane == 0) sh_red[warp] = lsum;
    __syncthreads();

    if (tid == 0) {
        float push = 0.0f;
        #pragma unroll
        for (int w = 0; w < NWRP; w++) push += sh_red[w];
        const float inv_n = 1.0f / (float)((size_t)NSEG * PPS);
        atomicAdd(out, (pull + push) * inv_n);
    }
}

extern "C" void kernel_launch(void* const* d_in, const int* in_sizes, int n_in,
                              void* d_out, int out_size)
{
    const float* outputs = (const float*)d_in[0];
    const int*   labels  = (const int*)d_in[1];
    float*       out     = (float*)d_out;

    lmnn_init_out<<<1, 1>>>(out);
    lmnn_kernel<<<NSEG, NTHR>>>(outputs, labels, out);
}

// round 4
// speedup vs baseline: 1.0610x; 1.0610x over previous
#include <cuda_runtime.h>

// LMNN loss on GB300 — R1 skeleton (max occupancy: 256 thr, 8 CTA/SM, 32 regs)
// + single-kernel last-block reduction (no init kernel) + streaming loads.
//
// outputs: [2048, 512, 128] f32, label_inds: [2048, 511] i32, out: scalar f32.
// Warp-per-point: lane l holds float4 of dims [4l,4l+4) -> each 512B point
// row is one coalesced LDG.128 (evict-first) per lane.

#define NSEG 2048
#define PPS  512
#define DDIM 128
#define NPTS 511   // PPS - 1
#define NTHR 256
#define NWRP 8

__device__ float        g_partial[NSEG];
__device__ unsigned int g_ticket = 0;   // self-resetting via atomicInc wrap

__global__ __launch_bounds__(NTHR, 8)
void lmnn_kernel(const float* __restrict__ outputs,
                 const int*   __restrict__ labels,
                 float*       __restrict__ out)
{
    __shared__ float sh_d2[NPTS];
    __shared__ int   sh_same[NPTS];
    __shared__ float sh_red[NWRP];
    __shared__ bool  sh_last;

    const int seg  = blockIdx.x;
    const int tid  = threadIdx.x;
    const int warp = tid >> 5;
    const int lane = tid & 31;

    const float4* base = reinterpret_cast<const float4*>(
        outputs + (size_t)seg * PPS * DDIM);

    // Center row: lane l owns dims [4l, 4l+4). Redundant per warp; L1/L2 hit.
    const float4 c = base[lane];

    // Same-label flags vs label of first point.
    const int* lab = labels + (size_t)seg * NPTS;
    const int lab0 = __ldg(lab);
    for (int j = tid; j < NPTS; j += NTHR)
        sh_same[j] = (__ldg(lab + j) == lab0);

    // d2 per point: warp w handles points w, w+8, w+16, ...
    // __ldcs: touched-once streaming data, evict-first in L1/L2.
    #pragma unroll 4
    for (int j = warp; j < NPTS; j += NWRP) {
        const float4 p = __ldcs(base + (j + 1) * (DDIM / 4) + lane);
        const float dx = p.x - c.x;
        const float dy = p.y - c.y;
        const float dz = p.z - c.z;
        const float dw = p.w - c.w;
        float s = dx * dx + dy * dy + dz * dz + dw * dw;
        #pragma unroll
        for (int o = 16; o > 0; o >>= 1)
            s += __shfl_xor_sync(0xffffffffu, s, o);
        if (lane == 0) sh_d2[j] = s;
    }
    __syncthreads();

    // pull_d = min d2 over same-label points (j=0 is always same-label).
    float lmin = __int_as_float(0x7f800000);  // +inf
    for (int j = tid; j < NPTS; j += NTHR)
        if (sh_same[j]) lmin = fminf(lmin, sh_d2[j]);
    #pragma unroll
    for (int o = 16; o > 0; o >>= 1)
        lmin = fminf(lmin, __shfl_xor_sync(0xffffffffu, lmin, o));
    if (lane == 0) sh_red[warp] = lmin;
    __syncthreads();

    float pull = sh_red[0];
    #pragma unroll
    for (int w = 1; w < NWRP; w++) pull = fminf(pull, sh_red[w]);
    const float margin = 1.0f + pull;

    // push = sum over diff-label points of max(margin - d2, 0).
    float lsum = 0.0f;
    for (int j = tid; j < NPTS; j += NTHR)
        if (!sh_same[j]) lsum += fmaxf(margin - sh_d2[j], 0.0f);
    #pragma unroll
    for (int o = 16; o > 0; o >>= 1)
        lsum += __shfl_xor_sync(0xffffffffu, lsum, o);
    __syncthreads();          // all reads of sh_red (pull) done before reuse
    if (lane == 0) sh_red[warp] = lsum;
    __syncthreads();

    // Publish per-segment partial; last CTA to finish reduces all of them.
    if (tid == 0) {
        float push = 0.0f;
        #pragma unroll
        for (int w = 0; w < NWRP; w++) push += sh_red[w];
        g_partial[seg] = pull + push;
        __threadfence();
        // atomicInc wraps to 0 when old == NSEG-1 -> counter self-resets,
        // so every graph replay sees the same initial state (deterministic).
        const unsigned int old = atomicInc(&g_ticket, NSEG - 1);
        sh_last = (old == NSEG - 1);
    }
    __syncthreads();

    if (sh_last) {
        // This CTA observed all 2048 partials published (fence + atomic order).
        float acc = 0.0f;
        const volatile float* vp = g_partial;
        #pragma unroll
        for (int i = tid; i < NSEG; i += NTHR)
            acc += vp[i];
        #pragma unroll
        for (int o = 16; o > 0; o >>= 1)
            acc += __shfl_xor_sync(0xffffffffu, acc, o);
        if (lane == 0) sh_red[warp] = acc;
        __syncthreads();
        if (tid == 0) {
            float tot = 0.0f;
            #pragma unroll
            for (int w = 0; w < NWRP; w++) tot += sh_red[w];
            *out = tot / (float)((size_t)NSEG * PPS);
        }
    }
}

extern "C" void kernel_launch(void* const* d_in, const int* in_sizes, int n_in,
                              void* d_out, int out_size)
{
    const float* outputs = (const float*)d_in[0];
    const int*   labels  = (const int*)d_in[1];
    float*       out     = (float*)d_out;

    lmnn_kernel<<<NSEG, NTHR>>>(outputs, labels, out);
}